// round 15
// baseline (speedup 1.0000x reference)
#include <cuda_runtime.h>
#include <cuda_bf16.h>
#include <math.h>

#define NN 50000
#define EE 1600000
#define FF 64
#define HH 128
#define AA 16
#define PAD 96           // per-dst bucket capacity; P(deg>96) ~ e^-42 per node

// ---------------- scratch (device globals; no allocation allowed) ----------
__device__ __align__(16) __nv_bfloat16 g_hb[NN * HH];  // h (gather operand, bf16)
__device__ __align__(16) float g_out[NN * HH];         // gat layer output (fp32)
__device__ float g_ssrc[NN];
__device__ float g_sdst[NN];
__device__ int   g_cnt[NN];          // zero-init at load; re-zeroed in k_pool
__device__ __align__(16) uint2 g_e1[NN * PAD];   // {src, eac(layer1) bits}
__device__ __align__(16) uint2 g_e2[NN * PAD];   // {src, eac(layer2) bits}
__device__ float g_v[4];
__device__ float g_pooled[HH];       // zero-init at load; re-zeroed in k_head

__device__ __forceinline__ unsigned to_tf32(float x) {
    unsigned r;
    asm("cvt.rna.tf32.f32 %0, %1;" : "=r"(r) : "f"(x));
    return r;
}

// v = We @ a_e for both layers (ED=2)
__global__ void k_v(const float* __restrict__ We1, const float* __restrict__ ae1,
                    const float* __restrict__ We2, const float* __restrict__ ae2) {
    __shared__ float red[128];
    int t = threadIdx.x;
    float vals[4] = { We1[t] * ae1[t], We1[128 + t] * ae1[t],
                      We2[t] * ae2[t], We2[128 + t] * ae2[t] };
    for (int k = 0; k < 4; k++) {
        red[t] = vals[k];
        __syncthreads();
        for (int off = 64; off > 0; off >>= 1) {
            if (t < off) red[t] += red[t + off];
            __syncthreads();
        }
        if (t == 0) g_v[k] = red[0];
        __syncthreads();
    }
}

// scatter edges directly into padded per-dst buckets (no count/scan passes)
__global__ void k_scatter(const int* __restrict__ ei, const float* __restrict__ ea) {
    int e = blockIdx.x * blockDim.x + threadIdx.x;
    if (e >= EE) return;
    int s = ei[e];
    int d = ei[EE + e];
    float e0 = ea[2 * e + 0], e1 = ea[2 * e + 1];
    int pos = atomicAdd(&g_cnt[d], 1);
    if (pos < PAD) {
        size_t idx = (size_t)d * PAD + pos;
        g_e1[idx] = make_uint2((unsigned)s, __float_as_uint(e0 * g_v[0] + e1 * g_v[1]));
        g_e2[idx] = make_uint2((unsigned)s, __float_as_uint(e0 * g_v[2] + e1 * g_v[3]));
    }
}

// ---------------- tf32 tensor-core GEMM: h = A[N,K](f32) @ W[K,128](f32) ---
// 64x128 block tile, 8 warps (2m x 4n), warp tile 32x32 via mma.m16n8k8.tf32.
template <int K>
__global__ __launch_bounds__(256) void k_gemm_mma(
    const float* __restrict__ A,
    const float* __restrict__ W,
    const float* __restrict__ as_, const float* __restrict__ ad_,
    __nv_bfloat16* __restrict__ Hout) {
    __shared__ unsigned As[64][20];     // stride 20: conflict-free frag loads
    __shared__ unsigned Bs[16][136];    // stride 136: conflict-free frag loads
    __shared__ float sds[64], sdd[64];
    int tid = threadIdx.x;
    int lane = tid & 31, wid = tid >> 5;
    int wm = wid & 1, wn = wid >> 1;    // 2 x 4 warp grid
    int r0 = blockIdx.x * 64;
    int g = lane >> 2, tc = lane & 3;
    int wr = wm * 32, wc = wn * 32;

    if (tid < 64) { sds[tid] = 0.f; sdd[tid] = 0.f; }

    float c[2][4][4];
#pragma unroll
    for (int mf = 0; mf < 2; mf++)
#pragma unroll
        for (int nf = 0; nf < 4; nf++)
#pragma unroll
            for (int r = 0; r < 4; r++) c[mf][nf][r] = 0.f;

    int arow = tid >> 2, acol = (tid & 3) * 4;    // A: 64 rows x 16 cols/step
    int brow = tid >> 4, bcol = (tid & 15) * 8;   // B: 16 rows x 128 cols

    for (int k0 = 0; k0 < K; k0 += 16) {
        float4 xa = make_float4(0.f, 0.f, 0.f, 0.f);
        if (r0 + arow < NN) xa = *(const float4*)&A[(size_t)(r0 + arow) * K + k0 + acol];
        uint4 ua = make_uint4(to_tf32(xa.x), to_tf32(xa.y), to_tf32(xa.z), to_tf32(xa.w));
        *(uint4*)&As[arow][acol] = ua;

        float4 w0 = *(const float4*)&W[(size_t)(k0 + brow) * HH + bcol];
        float4 w1 = *(const float4*)&W[(size_t)(k0 + brow) * HH + bcol + 4];
        uint4 ub0 = make_uint4(to_tf32(w0.x), to_tf32(w0.y), to_tf32(w0.z), to_tf32(w0.w));
        uint4 ub1 = make_uint4(to_tf32(w1.x), to_tf32(w1.y), to_tf32(w1.z), to_tf32(w1.w));
        *(uint4*)&Bs[brow][bcol]     = ub0;
        *(uint4*)&Bs[brow][bcol + 4] = ub1;
        __syncthreads();

#pragma unroll
        for (int kb = 0; kb < 16; kb += 8) {
            unsigned a[2][4], b[4][2];
#pragma unroll
            for (int mf = 0; mf < 2; mf++) {
                a[mf][0] = As[wr + mf * 16 + g][kb + tc];
                a[mf][1] = As[wr + mf * 16 + g + 8][kb + tc];
                a[mf][2] = As[wr + mf * 16 + g][kb + tc + 4];
                a[mf][3] = As[wr + mf * 16 + g + 8][kb + tc + 4];
            }
#pragma unroll
            for (int nf = 0; nf < 4; nf++) {
                b[nf][0] = Bs[kb + tc][wc + nf * 8 + g];
                b[nf][1] = Bs[kb + tc + 4][wc + nf * 8 + g];
            }
#pragma unroll
            for (int mf = 0; mf < 2; mf++)
#pragma unroll
                for (int nf = 0; nf < 4; nf++)
                    asm volatile(
                        "mma.sync.aligned.m16n8k8.row.col.f32.tf32.tf32.f32 "
                        "{%0,%1,%2,%3},{%4,%5,%6,%7},{%8,%9},{%0,%1,%2,%3};"
                        : "+f"(c[mf][nf][0]), "+f"(c[mf][nf][1]),
                          "+f"(c[mf][nf][2]), "+f"(c[mf][nf][3])
                        : "r"(a[mf][0]), "r"(a[mf][1]), "r"(a[mf][2]), "r"(a[mf][3]),
                          "r"(b[nf][0]), "r"(b[nf][1]));
        }
        __syncthreads();
    }

    // epilogue: bf16 store + fused attention dots
    float asr[4][2], adr[4][2];
#pragma unroll
    for (int nf = 0; nf < 4; nf++) {
        int col = wc + nf * 8 + tc * 2;
        asr[nf][0] = as_[col]; asr[nf][1] = as_[col + 1];
        adr[nf][0] = ad_[col]; adr[nf][1] = ad_[col + 1];
    }
#pragma unroll
    for (int mf = 0; mf < 2; mf++) {
#pragma unroll
        for (int half = 0; half < 2; half++) {
            int lrow = wr + mf * 16 + g + half * 8;
            int row = r0 + lrow;
            float ps = 0.f, pd = 0.f;
#pragma unroll
            for (int nf = 0; nf < 4; nf++) {
                float v0 = c[mf][nf][half * 2 + 0];
                float v1 = c[mf][nf][half * 2 + 1];
                ps += v0 * asr[nf][0] + v1 * asr[nf][1];
                pd += v0 * adr[nf][0] + v1 * adr[nf][1];
                if (row < NN) {
                    __nv_bfloat162 pk = __floats2bfloat162_rn(v0, v1);
                    int col = wc + nf * 8 + tc * 2;
                    *(unsigned*)&Hout[(size_t)row * HH + col] = *(unsigned*)&pk;
                }
            }
            ps += __shfl_xor_sync(0xffffffffu, ps, 1);
            ps += __shfl_xor_sync(0xffffffffu, ps, 2);
            pd += __shfl_xor_sync(0xffffffffu, pd, 1);
            pd += __shfl_xor_sync(0xffffffffu, pd, 2);
            if (tc == 0) { atomicAdd(&sds[lrow], ps); atomicAdd(&sdd[lrow], pd); }
        }
    }
    __syncthreads();
    if (tid < 64 && r0 + tid < NN) {
        g_ssrc[r0 + tid] = sds[tid];
        g_sdst[r0 + tid] = sdd[tid];
    }
}

__device__ __forceinline__ float lrelu(float x) { return x > 0.f ? x : 0.2f * x; }

__device__ __forceinline__ float4 bf16x4_ld(const __nv_bfloat16* p) {
    uint2 u = *(const uint2*)p;
    float2 f0 = __bfloat1622float2(*(__nv_bfloat162*)&u.x);
    float2 f1 = __bfloat1622float2(*(__nv_bfloat162*)&u.y);
    return make_float4(f0.x, f0.y, f1.x, f1.y);
}

// fused GAT aggregation: one warp/node, bf16 gathers (rolled loop — measured
// optimal). Softmax WITHOUT max shift (logits ~ N(0,1.7), exp safe in fp32).
// Edges come from the padded per-dst bucket at n*PAD, count in g_cnt[n].
__global__ __launch_bounds__(256) void k_gat(const float* __restrict__ bias,
                                             const uint2* __restrict__ edges) {
    int warp = (blockIdx.x * 256 + threadIdx.x) >> 5;
    int lane = threadIdx.x & 31;
    if (warp >= NN) return;
    int n = warp;
    int cnt = min(g_cnt[n], PAD);
    size_t base = (size_t)n * PAD;
    float sd = g_sdst[n];

    float4 acc = make_float4(0.f, 0.f, 0.f, 0.f);
    float denom = 0.f, eacsum = 0.f;

    for (int start = 0; start < cnt; start += 32) {
        int i = start + lane;
        float p = 0.f;
        int s = 0;
        if (i < cnt) {
            uint2 ed = edges[base + i];
            s = (int)ed.x;
            float ec = __uint_as_float(ed.y);
            p = __expf(lrelu(g_ssrc[s] + sd + ec));
            eacsum += ec;
        }
        denom += p;
        int c = min(32, cnt - start);
        for (int j = 0; j < c; j++) {
            float pj = __shfl_sync(0xffffffffu, p, j);
            int sj = __shfl_sync(0xffffffffu, s, j);
            float4 hv = bf16x4_ld(&g_hb[(size_t)sj * HH + lane * 4]);
            acc.x += pj * hv.x; acc.y += pj * hv.y;
            acc.z += pj * hv.z; acc.w += pj * hv.w;
        }
    }
#pragma unroll
    for (int off = 16; off; off >>= 1) {
        denom  += __shfl_xor_sync(0xffffffffu, denom, off);
        eacsum += __shfl_xor_sync(0xffffffffu, eacsum, off);
    }

    // self edge (ea = per-dst mean => eac_self = sum(eac)/cnt)
    float cntf = fmaxf((float)cnt, 1.f);
    float ps = __expf(lrelu(g_ssrc[n] + sd + eacsum / cntf));
    float4 hn = bf16x4_ld(&g_hb[(size_t)n * HH + lane * 4]);
    denom += ps;
    acc.x += ps * hn.x;
    acc.y += ps * hn.y;
    acc.z += ps * hn.z;
    acc.w += ps * hn.w;

    float inv = 1.f / (denom + 1e-16f);
    float4 bb = *(const float4*)&bias[lane * 4];
    float4 o;
    o.x = fmaxf(acc.x * inv + bb.x, 0.f);
    o.y = fmaxf(acc.y * inv + bb.y, 0.f);
    o.z = fmaxf(acc.z * inv + bb.z, 0.f);
    o.w = fmaxf(acc.w * inv + bb.w, 0.f);
    *(float4*)&g_out[(size_t)n * HH + lane * 4] = o;
}

// column-sum over rows (mean pool numerator); also re-zeroes g_cnt for the
// next replay (runs after gat2, the last reader of g_cnt)
__global__ void k_pool() {
    int t = threadIdx.x;
    int r0 = blockIdx.x * 128;
    int r1 = min(r0 + 128, NN);
    float acc = 0.f;
    for (int r = r0; r < r1; r++) acc += g_out[r * HH + t];
    atomicAdd(&g_pooled[t], acc);
    if (r0 + t < NN) g_cnt[r0 + t] = 0;
}

// final head; re-zeroes g_pooled after its last read (for the next replay)
__global__ void k_head(const float* __restrict__ Wfc, const float* __restrict__ bfc,
                       float* __restrict__ out) {
    int warp = threadIdx.x >> 5;
    int lane = threadIdx.x & 31;
    float sum = 0.f;
    for (int h = lane; h < HH; h += 32) sum += g_pooled[h] * Wfc[h * AA + warp];
#pragma unroll
    for (int off = 16; off; off >>= 1) sum += __shfl_xor_sync(0xffffffffu, sum, off);
    if (lane == 0) out[warp] = tanhf(sum * (1.0f / NN) + bfc[warp]);
    __syncthreads();
    if (threadIdx.x < HH) g_pooled[threadIdx.x] = 0.f;
}

// ---------------- launch ----------------------------------------------------
extern "C" void kernel_launch(void* const* d_in, const int* in_sizes, int n_in,
                              void* d_out, int out_size) {
    const float* x      = (const float*)d_in[0];
    const int*   ei     = (const int*)d_in[1];
    const float* ea     = (const float*)d_in[2];
    const float* W1     = (const float*)d_in[3];
    const float* We1    = (const float*)d_in[4];
    const float* asrc1  = (const float*)d_in[5];
    const float* adst1  = (const float*)d_in[6];
    const float* aedge1 = (const float*)d_in[7];
    const float* b1     = (const float*)d_in[8];
    const float* W2     = (const float*)d_in[9];
    const float* We2    = (const float*)d_in[10];
    const float* asrc2  = (const float*)d_in[11];
    const float* adst2  = (const float*)d_in[12];
    const float* aedge2 = (const float*)d_in[13];
    const float* b2     = (const float*)d_in[14];
    const float* Wfc    = (const float*)d_in[15];
    const float* bfc    = (const float*)d_in[16];
    float* out = (float*)d_out;

    void* p;
    cudaGetSymbolAddress(&p, g_out); const float* out_h = (const float*)p;
    cudaGetSymbolAddress(&p, g_hb);  __nv_bfloat16* hb = (__nv_bfloat16*)p;
    cudaGetSymbolAddress(&p, g_e1);  const uint2* e1 = (const uint2*)p;
    cudaGetSymbolAddress(&p, g_e2);  const uint2* e2 = (const uint2*)p;

    // side stream + events (created once; no device memory involved)
    static cudaStream_t s1 = nullptr;
    static cudaEvent_t ev_fork = nullptr, ev_v = nullptr, ev_join = nullptr;
    if (!s1) {
        cudaStreamCreateWithFlags(&s1, cudaStreamNonBlocking);
        cudaEventCreateWithFlags(&ev_fork, cudaEventDisableTiming);
        cudaEventCreateWithFlags(&ev_v,    cudaEventDisableTiming);
        cudaEventCreateWithFlags(&ev_join, cudaEventDisableTiming);
    }

    const int EB  = (EE + 255) / 256;
    const int GB  = (NN + 63) / 64;    // gemm blocks
    const int NWB = NN / 8;            // one warp per node

    // fork: scatter on s1 (after k_v), k_v + layer-1 GEMM on stream0
    cudaEventRecord(ev_fork, 0);
    cudaStreamWaitEvent(s1, ev_fork, 0);

    k_v<<<1, 128>>>(We1, aedge1, We2, aedge2);
    cudaEventRecord(ev_v, 0);
    k_gemm_mma<FF><<<GB, 256>>>(x, W1, asrc1, adst1, hb);

    cudaStreamWaitEvent(s1, ev_v, 0);
    k_scatter<<<EB, 256, 0, s1>>>(ei, ea);

    // join: gat layer 1 needs both the edge buckets and the layer-1 GEMM
    cudaEventRecord(ev_join, s1);
    cudaStreamWaitEvent(0, ev_join, 0);

    k_gat<<<NWB, 256>>>(b1, e1);

    // layer 2
    k_gemm_mma<HH><<<GB, 256>>>(out_h, W2, asrc2, adst2, hb);
    k_gat<<<NWB, 256>>>(b2, e2);

    // pool + head
    k_pool<<<(NN + 127) / 128, 128>>>();
    k_head<<<1, 512>>>(Wfc, bfc, out);
}

// round 16
// speedup vs baseline: 1.5536x; 1.5536x over previous
#include <cuda_runtime.h>
#include <cuda_bf16.h>
#include <math.h>

#define NN 50000
#define EE 1600000
#define FF 64
#define HH 128
#define AA 16
#define NB 49            // ceil(NN/1024)

// ---------------- scratch (device globals; no allocation allowed) ----------
__device__ __align__(16) __nv_bfloat16 g_hb[NN * HH];  // h (gather operand, bf16)
__device__ __align__(16) float g_out[NN * HH];         // gat layer output (fp32)
__device__ float g_ssrc[NN];
__device__ float g_sdst[NN];
__device__ int   g_cnt[NN];          // zero-init at load; re-zeroed in k_scan3
__device__ int   g_rowptr[NN + 1];
__device__ int   g_writeptr[NN];
__device__ __align__(16) uint2 g_e1[EE];   // {src, eac(layer1) bits}
__device__ __align__(16) uint2 g_e2[EE];   // {src, eac(layer2) bits}
__device__ int   g_bsum[64];
__device__ float g_v[4];
__device__ float g_pooled[HH];       // zero-init at load; re-zeroed in k_scan3

__device__ __forceinline__ unsigned to_tf32(float x) {
    unsigned r;
    asm("cvt.rna.tf32.f32 %0, %1;" : "=r"(r) : "f"(x));
    return r;
}

// v = We @ a_e for both layers (ED=2)
__global__ void k_v(const float* __restrict__ We1, const float* __restrict__ ae1,
                    const float* __restrict__ We2, const float* __restrict__ ae2) {
    __shared__ float red[128];
    int t = threadIdx.x;
    float vals[4] = { We1[t] * ae1[t], We1[128 + t] * ae1[t],
                      We2[t] * ae2[t], We2[128 + t] * ae2[t] };
    for (int k = 0; k < 4; k++) {
        red[t] = vals[k];
        __syncthreads();
        for (int off = 64; off > 0; off >>= 1) {
            if (t < off) red[t] += red[t + off];
            __syncthreads();
        }
        if (t == 0) g_v[k] = red[0];
        __syncthreads();
    }
}

// count in-degree per dst (one int atomic per edge)
__global__ void k_count(const int* __restrict__ ei) {
    int e = blockIdx.x * blockDim.x + threadIdx.x;
    if (e >= EE) return;
    atomicAdd(&g_cnt[ei[EE + e]], 1);
}

__global__ void k_scan1() {
    __shared__ int s[1024];
    int tid = threadIdx.x;
    int i = blockIdx.x * 1024 + tid;
    int c = (i < NN) ? g_cnt[i] : 0;
    s[tid] = c;
    __syncthreads();
    for (int off = 1; off < 1024; off <<= 1) {
        int t = (tid >= off) ? s[tid - off] : 0;
        __syncthreads();
        s[tid] += t;
        __syncthreads();
    }
    if (i < NN) g_rowptr[i] = s[tid] - c;
    if (tid == 1023) g_bsum[blockIdx.x] = s[1023];
}

// finalize rowptr (each block redundantly scans the 49 block sums);
// also re-zero g_cnt / g_pooled for the next graph replay
__global__ void k_scan3() {
    __shared__ int boff[64];
    if (threadIdx.x == 0) {
        int a = 0;
        for (int b = 0; b < NB; b++) { boff[b] = a; a += g_bsum[b]; }
    }
    __syncthreads();
    int i = blockIdx.x * 1024 + threadIdx.x;
    if (i < NN) {
        int r = g_rowptr[i] + boff[blockIdx.x];
        g_rowptr[i] = r;
        g_writeptr[i] = r;
        g_cnt[i] = 0;
    }
    if (i < HH) g_pooled[i] = 0.f;
    if (i == 0) g_rowptr[NN] = EE;
}

// scatter edges into dst-sorted CSR; two 8B packed stores per edge
__global__ void k_scatter(const int* __restrict__ ei, const float* __restrict__ ea) {
    int e = blockIdx.x * blockDim.x + threadIdx.x;
    if (e >= EE) return;
    int s = ei[e];
    int d = ei[EE + e];
    float e0 = ea[2 * e + 0], e1 = ea[2 * e + 1];
    int pos = atomicAdd(&g_writeptr[d], 1);
    g_e1[pos] = make_uint2((unsigned)s, __float_as_uint(e0 * g_v[0] + e1 * g_v[1]));
    g_e2[pos] = make_uint2((unsigned)s, __float_as_uint(e0 * g_v[2] + e1 * g_v[3]));
}

// ---------------- tf32 tensor-core GEMM: h = A[N,K](f32) @ W[K,128](f32) ---
// 64x128 block tile, 8 warps (2m x 4n), warp tile 32x32 via mma.m16n8k8.tf32.
template <int K>
__global__ __launch_bounds__(256) void k_gemm_mma(
    const float* __restrict__ A,
    const float* __restrict__ W,
    const float* __restrict__ as_, const float* __restrict__ ad_,
    __nv_bfloat16* __restrict__ Hout) {
    __shared__ unsigned As[64][20];     // stride 20: conflict-free frag loads
    __shared__ unsigned Bs[16][136];    // stride 136: conflict-free frag loads
    __shared__ float sds[64], sdd[64];
    int tid = threadIdx.x;
    int lane = tid & 31, wid = tid >> 5;
    int wm = wid & 1, wn = wid >> 1;    // 2 x 4 warp grid
    int r0 = blockIdx.x * 64;
    int g = lane >> 2, tc = lane & 3;
    int wr = wm * 32, wc = wn * 32;

    if (tid < 64) { sds[tid] = 0.f; sdd[tid] = 0.f; }

    float c[2][4][4];
#pragma unroll
    for (int mf = 0; mf < 2; mf++)
#pragma unroll
        for (int nf = 0; nf < 4; nf++)
#pragma unroll
            for (int r = 0; r < 4; r++) c[mf][nf][r] = 0.f;

    int arow = tid >> 2, acol = (tid & 3) * 4;    // A: 64 rows x 16 cols/step
    int brow = tid >> 4, bcol = (tid & 15) * 8;   // B: 16 rows x 128 cols

    for (int k0 = 0; k0 < K; k0 += 16) {
        float4 xa = make_float4(0.f, 0.f, 0.f, 0.f);
        if (r0 + arow < NN) xa = *(const float4*)&A[(size_t)(r0 + arow) * K + k0 + acol];
        uint4 ua = make_uint4(to_tf32(xa.x), to_tf32(xa.y), to_tf32(xa.z), to_tf32(xa.w));
        *(uint4*)&As[arow][acol] = ua;

        float4 w0 = *(const float4*)&W[(size_t)(k0 + brow) * HH + bcol];
        float4 w1 = *(const float4*)&W[(size_t)(k0 + brow) * HH + bcol + 4];
        uint4 ub0 = make_uint4(to_tf32(w0.x), to_tf32(w0.y), to_tf32(w0.z), to_tf32(w0.w));
        uint4 ub1 = make_uint4(to_tf32(w1.x), to_tf32(w1.y), to_tf32(w1.z), to_tf32(w1.w));
        *(uint4*)&Bs[brow][bcol]     = ub0;
        *(uint4*)&Bs[brow][bcol + 4] = ub1;
        __syncthreads();

#pragma unroll
        for (int kb = 0; kb < 16; kb += 8) {
            unsigned a[2][4], b[4][2];
#pragma unroll
            for (int mf = 0; mf < 2; mf++) {
                a[mf][0] = As[wr + mf * 16 + g][kb + tc];
                a[mf][1] = As[wr + mf * 16 + g + 8][kb + tc];
                a[mf][2] = As[wr + mf * 16 + g][kb + tc + 4];
                a[mf][3] = As[wr + mf * 16 + g + 8][kb + tc + 4];
            }
#pragma unroll
            for (int nf = 0; nf < 4; nf++) {
                b[nf][0] = Bs[kb + tc][wc + nf * 8 + g];
                b[nf][1] = Bs[kb + tc + 4][wc + nf * 8 + g];
            }
#pragma unroll
            for (int mf = 0; mf < 2; mf++)
#pragma unroll
                for (int nf = 0; nf < 4; nf++)
                    asm volatile(
                        "mma.sync.aligned.m16n8k8.row.col.f32.tf32.tf32.f32 "
                        "{%0,%1,%2,%3},{%4,%5,%6,%7},{%8,%9},{%0,%1,%2,%3};"
                        : "+f"(c[mf][nf][0]), "+f"(c[mf][nf][1]),
                          "+f"(c[mf][nf][2]), "+f"(c[mf][nf][3])
                        : "r"(a[mf][0]), "r"(a[mf][1]), "r"(a[mf][2]), "r"(a[mf][3]),
                          "r"(b[nf][0]), "r"(b[nf][1]));
        }
        __syncthreads();
    }

    // epilogue: bf16 store + fused attention dots
    float asr[4][2], adr[4][2];
#pragma unroll
    for (int nf = 0; nf < 4; nf++) {
        int col = wc + nf * 8 + tc * 2;
        asr[nf][0] = as_[col]; asr[nf][1] = as_[col + 1];
        adr[nf][0] = ad_[col]; adr[nf][1] = ad_[col + 1];
    }
#pragma unroll
    for (int mf = 0; mf < 2; mf++) {
#pragma unroll
        for (int half = 0; half < 2; half++) {
            int lrow = wr + mf * 16 + g + half * 8;
            int row = r0 + lrow;
            float ps = 0.f, pd = 0.f;
#pragma unroll
            for (int nf = 0; nf < 4; nf++) {
                float v0 = c[mf][nf][half * 2 + 0];
                float v1 = c[mf][nf][half * 2 + 1];
                ps += v0 * asr[nf][0] + v1 * asr[nf][1];
                pd += v0 * adr[nf][0] + v1 * adr[nf][1];
                if (row < NN) {
                    __nv_bfloat162 pk = __floats2bfloat162_rn(v0, v1);
                    int col = wc + nf * 8 + tc * 2;
                    *(unsigned*)&Hout[(size_t)row * HH + col] = *(unsigned*)&pk;
                }
            }
            ps += __shfl_xor_sync(0xffffffffu, ps, 1);
            ps += __shfl_xor_sync(0xffffffffu, ps, 2);
            pd += __shfl_xor_sync(0xffffffffu, pd, 1);
            pd += __shfl_xor_sync(0xffffffffu, pd, 2);
            if (tc == 0) { atomicAdd(&sds[lrow], ps); atomicAdd(&sdd[lrow], pd); }
        }
    }
    __syncthreads();
    if (tid < 64 && r0 + tid < NN) {
        g_ssrc[r0 + tid] = sds[tid];
        g_sdst[r0 + tid] = sdd[tid];
    }
}

__device__ __forceinline__ float lrelu(float x) { return x > 0.f ? x : 0.2f * x; }

__device__ __forceinline__ float4 bf16x4_ld(const __nv_bfloat16* p) {
    uint2 u = *(const uint2*)p;
    float2 f0 = __bfloat1622float2(*(__nv_bfloat162*)&u.x);
    float2 f1 = __bfloat1622float2(*(__nv_bfloat162*)&u.y);
    return make_float4(f0.x, f0.y, f1.x, f1.y);
}

// fused GAT aggregation: one warp/node, bf16 gathers (rolled loop — measured
// optimal). Softmax WITHOUT max shift (logits ~ N(0,1.7), exp safe in fp32).
__global__ __launch_bounds__(256) void k_gat(const float* __restrict__ bias,
                                             const uint2* __restrict__ edges) {
    int warp = (blockIdx.x * 256 + threadIdx.x) >> 5;
    int lane = threadIdx.x & 31;
    if (warp >= NN) return;
    int n = warp;
    int rp0 = g_rowptr[n], rp1 = g_rowptr[n + 1];
    float sd = g_sdst[n];

    float4 acc = make_float4(0.f, 0.f, 0.f, 0.f);
    float denom = 0.f, eacsum = 0.f;

    for (int start = rp0; start < rp1; start += 32) {
        int i = start + lane;
        float p = 0.f;
        int s = 0;
        if (i < rp1) {
            uint2 ed = edges[i];
            s = (int)ed.x;
            float ec = __uint_as_float(ed.y);
            p = __expf(lrelu(g_ssrc[s] + sd + ec));
            eacsum += ec;
        }
        denom += p;
        int cnt = min(32, rp1 - start);
        for (int j = 0; j < cnt; j++) {
            float pj = __shfl_sync(0xffffffffu, p, j);
            int sj = __shfl_sync(0xffffffffu, s, j);
            float4 hv = bf16x4_ld(&g_hb[(size_t)sj * HH + lane * 4]);
            acc.x += pj * hv.x; acc.y += pj * hv.y;
            acc.z += pj * hv.z; acc.w += pj * hv.w;
        }
    }
#pragma unroll
    for (int off = 16; off; off >>= 1) {
        denom  += __shfl_xor_sync(0xffffffffu, denom, off);
        eacsum += __shfl_xor_sync(0xffffffffu, eacsum, off);
    }

    // self edge (ea = per-dst mean => eac_self = sum(eac)/cnt)
    float cntf = fmaxf((float)(rp1 - rp0), 1.f);
    float ps = __expf(lrelu(g_ssrc[n] + sd + eacsum / cntf));
    float4 hn = bf16x4_ld(&g_hb[(size_t)n * HH + lane * 4]);
    denom += ps;
    acc.x += ps * hn.x;
    acc.y += ps * hn.y;
    acc.z += ps * hn.z;
    acc.w += ps * hn.w;

    float inv = 1.f / (denom + 1e-16f);
    float4 bb = *(const float4*)&bias[lane * 4];
    float4 o;
    o.x = fmaxf(acc.x * inv + bb.x, 0.f);
    o.y = fmaxf(acc.y * inv + bb.y, 0.f);
    o.z = fmaxf(acc.z * inv + bb.z, 0.f);
    o.w = fmaxf(acc.w * inv + bb.w, 0.f);
    *(float4*)&g_out[(size_t)n * HH + lane * 4] = o;
}

// column-sum over rows (mean pool numerator)
__global__ void k_pool() {
    int t = threadIdx.x;
    int r0 = blockIdx.x * 128;
    int r1 = min(r0 + 128, NN);
    float acc = 0.f;
    for (int r = r0; r < r1; r++) acc += g_out[r * HH + t];
    atomicAdd(&g_pooled[t], acc);
}

__global__ void k_head(const float* __restrict__ Wfc, const float* __restrict__ bfc,
                       float* __restrict__ out) {
    int warp = threadIdx.x >> 5;
    int lane = threadIdx.x & 31;
    float sum = 0.f;
    for (int h = lane; h < HH; h += 32) sum += g_pooled[h] * Wfc[h * AA + warp];
#pragma unroll
    for (int off = 16; off; off >>= 1) sum += __shfl_xor_sync(0xffffffffu, sum, off);
    if (lane == 0) out[warp] = tanhf(sum * (1.0f / NN) + bfc[warp]);
}

// ---------------- launch ----------------------------------------------------
extern "C" void kernel_launch(void* const* d_in, const int* in_sizes, int n_in,
                              void* d_out, int out_size) {
    const float* x      = (const float*)d_in[0];
    const int*   ei     = (const int*)d_in[1];
    const float* ea     = (const float*)d_in[2];
    const float* W1     = (const float*)d_in[3];
    const float* We1    = (const float*)d_in[4];
    const float* asrc1  = (const float*)d_in[5];
    const float* adst1  = (const float*)d_in[6];
    const float* aedge1 = (const float*)d_in[7];
    const float* b1     = (const float*)d_in[8];
    const float* W2     = (const float*)d_in[9];
    const float* We2    = (const float*)d_in[10];
    const float* asrc2  = (const float*)d_in[11];
    const float* adst2  = (const float*)d_in[12];
    const float* aedge2 = (const float*)d_in[13];
    const float* b2     = (const float*)d_in[14];
    const float* Wfc    = (const float*)d_in[15];
    const float* bfc    = (const float*)d_in[16];
    float* out = (float*)d_out;

    void* p;
    cudaGetSymbolAddress(&p, g_out); const float* out_h = (const float*)p;
    cudaGetSymbolAddress(&p, g_hb);  __nv_bfloat16* hb = (__nv_bfloat16*)p;
    cudaGetSymbolAddress(&p, g_e1);  const uint2* e1 = (const uint2*)p;
    cudaGetSymbolAddress(&p, g_e2);  const uint2* e2 = (const uint2*)p;

    // side stream + events (created once; no device memory involved)
    static cudaStream_t s1 = nullptr;
    static cudaEvent_t ev_fork = nullptr, ev_v = nullptr, ev_join = nullptr;
    if (!s1) {
        cudaStreamCreateWithFlags(&s1, cudaStreamNonBlocking);
        cudaEventCreateWithFlags(&ev_fork, cudaEventDisableTiming);
        cudaEventCreateWithFlags(&ev_v,    cudaEventDisableTiming);
        cudaEventCreateWithFlags(&ev_join, cudaEventDisableTiming);
    }

    const int EB  = (EE + 255) / 256;
    const int GB  = (NN + 63) / 64;    // gemm blocks
    const int NWB = NN / 8;            // one warp per node

    // fork: CSR chain on s1, k_v + layer-1 GEMM on stream0
    cudaEventRecord(ev_fork, 0);
    cudaStreamWaitEvent(s1, ev_fork, 0);

    k_count<<<EB, 256, 0, s1>>>(ei);
    k_scan1<<<NB, 1024, 0, s1>>>();
    k_scan3<<<NB, 1024, 0, s1>>>();

    k_v<<<1, 128>>>(We1, aedge1, We2, aedge2);
    cudaEventRecord(ev_v, 0);
    k_gemm_mma<FF><<<GB, 256>>>(x, W1, asrc1, adst1, hb);

    cudaStreamWaitEvent(s1, ev_v, 0);
    k_scatter<<<EB, 256, 0, s1>>>(ei, ea);

    // join: gat layer 1 needs both the CSR and the layer-1 GEMM outputs
    cudaEventRecord(ev_join, s1);
    cudaStreamWaitEvent(0, ev_join, 0);

    k_gat<<<NWB, 256>>>(b1, e1);

    // layer 2
    k_gemm_mma<HH><<<GB, 256>>>(out_h, W2, asrc2, adst2, hb);
    k_gat<<<NWB, 256>>>(b2, e2);

    // pool + head
    k_pool<<<(NN + 127) / 128, 128>>>();
    k_head<<<1, 512>>>(Wfc, bfc, out);
}

// round 17
// speedup vs baseline: 1.5703x; 1.0107x over previous
#include <cuda_runtime.h>
#include <cuda_bf16.h>
#include <math.h>

#define NN 50000
#define EE 1600000
#define FF 64
#define HH 128
#define AA 16
#define NB 49            // ceil(NN/1024)

// ---------------- scratch (device globals; no allocation allowed) ----------
__device__ __align__(16) __nv_bfloat16 g_hb[NN * HH];  // h (gather operand, bf16)
__device__ __align__(16) float g_out[NN * HH];         // gat layer output (fp32)
__device__ float g_ssrc[NN];
__device__ float g_sdst[NN];
__device__ int   g_cnt[NN];          // zero-init at load; re-zeroed in k_scan3
__device__ int   g_rowptr[NN + 1];
__device__ int   g_writeptr[NN];
__device__ __align__(16) uint2 g_e1[EE];   // {src, eac(layer1) bits}
__device__ __align__(16) uint2 g_e2[EE];   // {src, eac(layer2) bits}
__device__ int   g_bsum[64];
__device__ float g_v[4];
__device__ float g_pooled[HH];       // zero-init at load; re-zeroed in k_scan3

__device__ __forceinline__ unsigned to_tf32(float x) {
    unsigned r;
    asm("cvt.rna.tf32.f32 %0, %1;" : "=r"(r) : "f"(x));
    return r;
}

// count in-degree per dst (one int atomic per edge).
// Block 0, warp 0 additionally computes v = We @ a_e for both layers (the
// later k_scatter on the same stream reads g_v after this kernel completes).
__global__ void k_count(const int* __restrict__ ei,
                        const float* __restrict__ We1, const float* __restrict__ ae1,
                        const float* __restrict__ We2, const float* __restrict__ ae2) {
    if (blockIdx.x == 0 && threadIdx.x < 32) {
        int l = threadIdx.x;
        float s0 = 0.f, s1 = 0.f, s2 = 0.f, s3 = 0.f;
#pragma unroll
        for (int h = l; h < HH; h += 32) {
            float a1 = ae1[h], a2 = ae2[h];
            s0 += We1[h] * a1;        s1 += We1[HH + h] * a1;
            s2 += We2[h] * a2;        s3 += We2[HH + h] * a2;
        }
#pragma unroll
        for (int off = 16; off; off >>= 1) {
            s0 += __shfl_xor_sync(0xffffffffu, s0, off);
            s1 += __shfl_xor_sync(0xffffffffu, s1, off);
            s2 += __shfl_xor_sync(0xffffffffu, s2, off);
            s3 += __shfl_xor_sync(0xffffffffu, s3, off);
        }
        if (l == 0) { g_v[0] = s0; g_v[1] = s1; g_v[2] = s2; g_v[3] = s3; }
    }
    int e = blockIdx.x * blockDim.x + threadIdx.x;
    if (e >= EE) return;
    atomicAdd(&g_cnt[ei[EE + e]], 1);
}

__global__ void k_scan1() {
    __shared__ int s[1024];
    int tid = threadIdx.x;
    int i = blockIdx.x * 1024 + tid;
    int c = (i < NN) ? g_cnt[i] : 0;
    s[tid] = c;
    __syncthreads();
    for (int off = 1; off < 1024; off <<= 1) {
        int t = (tid >= off) ? s[tid - off] : 0;
        __syncthreads();
        s[tid] += t;
        __syncthreads();
    }
    if (i < NN) g_rowptr[i] = s[tid] - c;
    if (tid == 1023) g_bsum[blockIdx.x] = s[1023];
}

// finalize rowptr (each block redundantly scans the 49 block sums);
// also re-zero g_cnt / g_pooled for the next graph replay
__global__ void k_scan3() {
    __shared__ int boff[64];
    if (threadIdx.x == 0) {
        int a = 0;
        for (int b = 0; b < NB; b++) { boff[b] = a; a += g_bsum[b]; }
    }
    __syncthreads();
    int i = blockIdx.x * 1024 + threadIdx.x;
    if (i < NN) {
        int r = g_rowptr[i] + boff[blockIdx.x];
        g_rowptr[i] = r;
        g_writeptr[i] = r;
        g_cnt[i] = 0;
    }
    if (i < HH) g_pooled[i] = 0.f;
    if (i == 0) g_rowptr[NN] = EE;
}

// scatter edges into dst-sorted CSR; two 8B packed stores per edge
__global__ void k_scatter(const int* __restrict__ ei, const float* __restrict__ ea) {
    int e = blockIdx.x * blockDim.x + threadIdx.x;
    if (e >= EE) return;
    int s = ei[e];
    int d = ei[EE + e];
    float e0 = ea[2 * e + 0], e1 = ea[2 * e + 1];
    int pos = atomicAdd(&g_writeptr[d], 1);
    g_e1[pos] = make_uint2((unsigned)s, __float_as_uint(e0 * g_v[0] + e1 * g_v[1]));
    g_e2[pos] = make_uint2((unsigned)s, __float_as_uint(e0 * g_v[2] + e1 * g_v[3]));
}

// ---------------- tf32 tensor-core GEMM: h = A[N,K](f32) @ W[K,128](f32) ---
// 64x128 block tile, 8 warps (2m x 4n), warp tile 32x32 via mma.m16n8k8.tf32.
template <int K>
__global__ __launch_bounds__(256) void k_gemm_mma(
    const float* __restrict__ A,
    const float* __restrict__ W,
    const float* __restrict__ as_, const float* __restrict__ ad_,
    __nv_bfloat16* __restrict__ Hout) {
    __shared__ unsigned As[64][20];     // stride 20: conflict-free frag loads
    __shared__ unsigned Bs[16][136];    // stride 136: conflict-free frag loads
    __shared__ float sds[64], sdd[64];
    int tid = threadIdx.x;
    int lane = tid & 31, wid = tid >> 5;
    int wm = wid & 1, wn = wid >> 1;    // 2 x 4 warp grid
    int r0 = blockIdx.x * 64;
    int g = lane >> 2, tc = lane & 3;
    int wr = wm * 32, wc = wn * 32;

    if (tid < 64) { sds[tid] = 0.f; sdd[tid] = 0.f; }

    float c[2][4][4];
#pragma unroll
    for (int mf = 0; mf < 2; mf++)
#pragma unroll
        for (int nf = 0; nf < 4; nf++)
#pragma unroll
            for (int r = 0; r < 4; r++) c[mf][nf][r] = 0.f;

    int arow = tid >> 2, acol = (tid & 3) * 4;    // A: 64 rows x 16 cols/step
    int brow = tid >> 4, bcol = (tid & 15) * 8;   // B: 16 rows x 128 cols

    for (int k0 = 0; k0 < K; k0 += 16) {
        float4 xa = make_float4(0.f, 0.f, 0.f, 0.f);
        if (r0 + arow < NN) xa = *(const float4*)&A[(size_t)(r0 + arow) * K + k0 + acol];
        uint4 ua = make_uint4(to_tf32(xa.x), to_tf32(xa.y), to_tf32(xa.z), to_tf32(xa.w));
        *(uint4*)&As[arow][acol] = ua;

        float4 w0 = *(const float4*)&W[(size_t)(k0 + brow) * HH + bcol];
        float4 w1 = *(const float4*)&W[(size_t)(k0 + brow) * HH + bcol + 4];
        uint4 ub0 = make_uint4(to_tf32(w0.x), to_tf32(w0.y), to_tf32(w0.z), to_tf32(w0.w));
        uint4 ub1 = make_uint4(to_tf32(w1.x), to_tf32(w1.y), to_tf32(w1.z), to_tf32(w1.w));
        *(uint4*)&Bs[brow][bcol]     = ub0;
        *(uint4*)&Bs[brow][bcol + 4] = ub1;
        __syncthreads();

#pragma unroll
        for (int kb = 0; kb < 16; kb += 8) {
            unsigned a[2][4], b[4][2];
#pragma unroll
            for (int mf = 0; mf < 2; mf++) {
                a[mf][0] = As[wr + mf * 16 + g][kb + tc];
                a[mf][1] = As[wr + mf * 16 + g + 8][kb + tc];
                a[mf][2] = As[wr + mf * 16 + g][kb + tc + 4];
                a[mf][3] = As[wr + mf * 16 + g + 8][kb + tc + 4];
            }
#pragma unroll
            for (int nf = 0; nf < 4; nf++) {
                b[nf][0] = Bs[kb + tc][wc + nf * 8 + g];
                b[nf][1] = Bs[kb + tc + 4][wc + nf * 8 + g];
            }
#pragma unroll
            for (int mf = 0; mf < 2; mf++)
#pragma unroll
                for (int nf = 0; nf < 4; nf++)
                    asm volatile(
                        "mma.sync.aligned.m16n8k8.row.col.f32.tf32.tf32.f32 "
                        "{%0,%1,%2,%3},{%4,%5,%6,%7},{%8,%9},{%0,%1,%2,%3};"
                        : "+f"(c[mf][nf][0]), "+f"(c[mf][nf][1]),
                          "+f"(c[mf][nf][2]), "+f"(c[mf][nf][3])
                        : "r"(a[mf][0]), "r"(a[mf][1]), "r"(a[mf][2]), "r"(a[mf][3]),
                          "r"(b[nf][0]), "r"(b[nf][1]));
        }
        __syncthreads();
    }

    // epilogue: bf16 store + fused attention dots
    float asr[4][2], adr[4][2];
#pragma unroll
    for (int nf = 0; nf < 4; nf++) {
        int col = wc + nf * 8 + tc * 2;
        asr[nf][0] = as_[col]; asr[nf][1] = as_[col + 1];
        adr[nf][0] = ad_[col]; adr[nf][1] = ad_[col + 1];
    }
#pragma unroll
    for (int mf = 0; mf < 2; mf++) {
#pragma unroll
        for (int half = 0; half < 2; half++) {
            int lrow = wr + mf * 16 + g + half * 8;
            int row = r0 + lrow;
            float ps = 0.f, pd = 0.f;
#pragma unroll
            for (int nf = 0; nf < 4; nf++) {
                float v0 = c[mf][nf][half * 2 + 0];
                float v1 = c[mf][nf][half * 2 + 1];
                ps += v0 * asr[nf][0] + v1 * asr[nf][1];
                pd += v0 * adr[nf][0] + v1 * adr[nf][1];
                if (row < NN) {
                    __nv_bfloat162 pk = __floats2bfloat162_rn(v0, v1);
                    int col = wc + nf * 8 + tc * 2;
                    *(unsigned*)&Hout[(size_t)row * HH + col] = *(unsigned*)&pk;
                }
            }
            ps += __shfl_xor_sync(0xffffffffu, ps, 1);
            ps += __shfl_xor_sync(0xffffffffu, ps, 2);
            pd += __shfl_xor_sync(0xffffffffu, pd, 1);
            pd += __shfl_xor_sync(0xffffffffu, pd, 2);
            if (tc == 0) { atomicAdd(&sds[lrow], ps); atomicAdd(&sdd[lrow], pd); }
        }
    }
    __syncthreads();
    if (tid < 64 && r0 + tid < NN) {
        g_ssrc[r0 + tid] = sds[tid];
        g_sdst[r0 + tid] = sdd[tid];
    }
}

__device__ __forceinline__ float lrelu(float x) { return x > 0.f ? x : 0.2f * x; }

__device__ __forceinline__ float4 bf16x4_ld(const __nv_bfloat16* p) {
    uint2 u = *(const uint2*)p;
    float2 f0 = __bfloat1622float2(*(__nv_bfloat162*)&u.x);
    float2 f1 = __bfloat1622float2(*(__nv_bfloat162*)&u.y);
    return make_float4(f0.x, f0.y, f1.x, f1.y);
}

// fused GAT aggregation: one warp/node, bf16 gathers (rolled loop — measured
// optimal). Softmax WITHOUT max shift (logits ~ N(0,1.7), exp safe in fp32).
__global__ __launch_bounds__(256) void k_gat(const float* __restrict__ bias,
                                             const uint2* __restrict__ edges) {
    int warp = (blockIdx.x * 256 + threadIdx.x) >> 5;
    int lane = threadIdx.x & 31;
    if (warp >= NN) return;
    int n = warp;
    int rp0 = g_rowptr[n], rp1 = g_rowptr[n + 1];
    float sd = g_sdst[n];

    float4 acc = make_float4(0.f, 0.f, 0.f, 0.f);
    float denom = 0.f, eacsum = 0.f;

    for (int start = rp0; start < rp1; start += 32) {
        int i = start + lane;
        float p = 0.f;
        int s = 0;
        if (i < rp1) {
            uint2 ed = edges[i];
            s = (int)ed.x;
            float ec = __uint_as_float(ed.y);
            p = __expf(lrelu(g_ssrc[s] + sd + ec));
            eacsum += ec;
        }
        denom += p;
        int cnt = min(32, rp1 - start);
        for (int j = 0; j < cnt; j++) {
            float pj = __shfl_sync(0xffffffffu, p, j);
            int sj = __shfl_sync(0xffffffffu, s, j);
            float4 hv = bf16x4_ld(&g_hb[(size_t)sj * HH + lane * 4]);
            acc.x += pj * hv.x; acc.y += pj * hv.y;
            acc.z += pj * hv.z; acc.w += pj * hv.w;
        }
    }
#pragma unroll
    for (int off = 16; off; off >>= 1) {
        denom  += __shfl_xor_sync(0xffffffffu, denom, off);
        eacsum += __shfl_xor_sync(0xffffffffu, eacsum, off);
    }

    // self edge (ea = per-dst mean => eac_self = sum(eac)/cnt)
    float cntf = fmaxf((float)(rp1 - rp0), 1.f);
    float ps = __expf(lrelu(g_ssrc[n] + sd + eacsum / cntf));
    float4 hn = bf16x4_ld(&g_hb[(size_t)n * HH + lane * 4]);
    denom += ps;
    acc.x += ps * hn.x;
    acc.y += ps * hn.y;
    acc.z += ps * hn.z;
    acc.w += ps * hn.w;

    float inv = 1.f / (denom + 1e-16f);
    float4 bb = *(const float4*)&bias[lane * 4];
    float4 o;
    o.x = fmaxf(acc.x * inv + bb.x, 0.f);
    o.y = fmaxf(acc.y * inv + bb.y, 0.f);
    o.z = fmaxf(acc.z * inv + bb.z, 0.f);
    o.w = fmaxf(acc.w * inv + bb.w, 0.f);
    *(float4*)&g_out[(size_t)n * HH + lane * 4] = o;
}

// column-sum over rows (mean pool numerator)
__global__ void k_pool() {
    int t = threadIdx.x;
    int r0 = blockIdx.x * 128;
    int r1 = min(r0 + 128, NN);
    float acc = 0.f;
    for (int r = r0; r < r1; r++) acc += g_out[r * HH + t];
    atomicAdd(&g_pooled[t], acc);
}

__global__ void k_head(const float* __restrict__ Wfc, const float* __restrict__ bfc,
                       float* __restrict__ out) {
    int warp = threadIdx.x >> 5;
    int lane = threadIdx.x & 31;
    float sum = 0.f;
    for (int h = lane; h < HH; h += 32) sum += g_pooled[h] * Wfc[h * AA + warp];
#pragma unroll
    for (int off = 16; off; off >>= 1) sum += __shfl_xor_sync(0xffffffffu, sum, off);
    if (lane == 0) out[warp] = tanhf(sum * (1.0f / NN) + bfc[warp]);
}

// ---------------- launch ----------------------------------------------------
extern "C" void kernel_launch(void* const* d_in, const int* in_sizes, int n_in,
                              void* d_out, int out_size) {
    const float* x      = (const float*)d_in[0];
    const int*   ei     = (const int*)d_in[1];
    const float* ea     = (const float*)d_in[2];
    const float* W1     = (const float*)d_in[3];
    const float* We1    = (const float*)d_in[4];
    const float* asrc1  = (const float*)d_in[5];
    const float* adst1  = (const float*)d_in[6];
    const float* aedge1 = (const float*)d_in[7];
    const float* b1     = (const float*)d_in[8];
    const float* W2     = (const float*)d_in[9];
    const float* We2    = (const float*)d_in[10];
    const float* asrc2  = (const float*)d_in[11];
    const float* adst2  = (const float*)d_in[12];
    const float* aedge2 = (const float*)d_in[13];
    const float* b2     = (const float*)d_in[14];
    const float* Wfc    = (const float*)d_in[15];
    const float* bfc    = (const float*)d_in[16];
    float* out = (float*)d_out;

    void* p;
    cudaGetSymbolAddress(&p, g_out); const float* out_h = (const float*)p;
    cudaGetSymbolAddress(&p, g_hb);  __nv_bfloat16* hb = (__nv_bfloat16*)p;
    cudaGetSymbolAddress(&p, g_e1);  const uint2* e1 = (const uint2*)p;
    cudaGetSymbolAddress(&p, g_e2);  const uint2* e2 = (const uint2*)p;

    // side stream + events (created once; no device memory involved)
    static cudaStream_t s1 = nullptr;
    static cudaEvent_t ev_fork = nullptr, ev_join = nullptr;
    if (!s1) {
        cudaStreamCreateWithFlags(&s1, cudaStreamNonBlocking);
        cudaEventCreateWithFlags(&ev_fork, cudaEventDisableTiming);
        cudaEventCreateWithFlags(&ev_join, cudaEventDisableTiming);
    }

    const int EB  = (EE + 255) / 256;
    const int GB  = (NN + 63) / 64;    // gemm blocks
    const int NWB = NN / 8;            // one warp per node

    // fork: CSR chain (count embeds the v computation) on s1, gemm1 on stream0
    cudaEventRecord(ev_fork, 0);
    cudaStreamWaitEvent(s1, ev_fork, 0);

    k_count<<<EB, 256, 0, s1>>>(ei, We1, aedge1, We2, aedge2);
    k_scan1<<<NB, 1024, 0, s1>>>();
    k_scan3<<<NB, 1024, 0, s1>>>();
    k_scatter<<<EB, 256, 0, s1>>>(ei, ea);

    k_gemm_mma<FF><<<GB, 256>>>(x, W1, asrc1, adst1, hb);

    // join: gat layer 1 needs both the CSR and the layer-1 GEMM outputs
    cudaEventRecord(ev_join, s1);
    cudaStreamWaitEvent(0, ev_join, 0);

    k_gat<<<NWB, 256>>>(b1, e1);

    // layer 2
    k_gemm_mma<HH><<<GB, 256>>>(out_h, W2, asrc2, adst2, hb);
    k_gat<<<NWB, 256>>>(b2, e2);

    // pool + head
    k_pool<<<(NN + 127) / 128, 128>>>();
    k_head<<<1, 512>>>(Wfc, bfc, out);
}